// round 7
// baseline (speedup 1.0000x reference)
#include <cuda_runtime.h>

// Haar pair transform: x (64, 4096, 256) f32 -> out (64, 2048, 512) f32
// Chunk-local identity mapping: each contiguous 512-float chunk transforms in place:
//   out[2f]   = (in[f] + in[f+256]) * INV_SQRT2
//   out[2f+1] = (in[f] - in[f+256]) * INV_SQRT2
//
// R7: persistent grid-stride version of the R4 shape. 592 CTAs (148 SMs x 4)
// of 512 threads each loop over ~14 thread-items. Across loop iterations the
// next pair of independent LDG.E.256 can issue while the previous iteration's
// STG.E.256 drain (software pipelining), removing per-CTA cold starts and
// wave-transition dead time. All accesses remain fully dense 256-bit ops
// with .cs single-touch policy.

__global__ void __launch_bounds__(512) haar_kernel(
    const float* __restrict__ in,
    float* __restrict__ out,
    int nt)                           // total thread-items = out floats / 16
{
    const float c = 0.70710678118654752440f;
    const int stride = gridDim.x * blockDim.x;

    for (int t = blockIdx.x * blockDim.x + threadIdx.x; t < nt; t += stride) {
        int chunk = t >> 5;           // 32 lanes cover one 512-float chunk
        int j     = t & 31;

        const float* p0 = in + ((long)chunk << 9) + (j << 3);   // x0: 8 floats
        const float* p1 = p0 + 256;                             // x1: 8 floats

        float a0,a1,a2,a3,a4,a5,a6,a7;
        float b0,b1,b2,b3,b4,b5,b6,b7;

        asm volatile("ld.global.cs.v8.f32 {%0,%1,%2,%3,%4,%5,%6,%7}, [%8];"
            : "=f"(a0),"=f"(a1),"=f"(a2),"=f"(a3),
              "=f"(a4),"=f"(a5),"=f"(a6),"=f"(a7)
            : "l"(p0));
        asm volatile("ld.global.cs.v8.f32 {%0,%1,%2,%3,%4,%5,%6,%7}, [%8];"
            : "=f"(b0),"=f"(b1),"=f"(b2),"=f"(b3),
              "=f"(b4),"=f"(b5),"=f"(b6),"=f"(b7)
            : "l"(p1));

        float* q = out + ((long)chunk << 9) + (j << 4);         // 16 contiguous outputs

        float o0 = (a0 + b0) * c, o1 = (a0 - b0) * c;
        float o2 = (a1 + b1) * c, o3 = (a1 - b1) * c;
        float o4 = (a2 + b2) * c, o5 = (a2 - b2) * c;
        float o6 = (a3 + b3) * c, o7 = (a3 - b3) * c;

        asm volatile("st.global.cs.v8.f32 [%0], {%1,%2,%3,%4,%5,%6,%7,%8};"
            :: "l"(q),
               "f"(o0),"f"(o1),"f"(o2),"f"(o3),
               "f"(o4),"f"(o5),"f"(o6),"f"(o7)
            : "memory");

        float s0 = (a4 + b4) * c, s1 = (a4 - b4) * c;
        float s2 = (a5 + b5) * c, s3 = (a5 - b5) * c;
        float s4 = (a6 + b6) * c, s5 = (a6 - b6) * c;
        float s6 = (a7 + b7) * c, s7 = (a7 - b7) * c;

        asm volatile("st.global.cs.v8.f32 [%0], {%1,%2,%3,%4,%5,%6,%7,%8};"
            :: "l"(q + 8),
               "f"(s0),"f"(s1),"f"(s2),"f"(s3),
               "f"(s4),"f"(s5),"f"(s6),"f"(s7)
            : "memory");
    }
}

extern "C" void kernel_launch(void* const* d_in, const int* in_sizes, int n_in,
                              void* d_out, int out_size)
{
    const float* x = (const float*)d_in[0];
    float* out = (float*)d_out;

    int nt = out_size / 16;          // 4,194,304 thread-items (16 floats out each)
    int threads = 512;
    int blocks = 148 * 4;            // persistent: 4 CTAs per SM

    haar_kernel<<<blocks, threads>>>(x, out, nt);
}

// round 8
// speedup vs baseline: 1.1130x; 1.1130x over previous
#include <cuda_runtime.h>

// Haar pair transform: x (64, 4096, 256) f32 -> out (64, 2048, 512) f32
// Chunk-local identity mapping: each contiguous 512-float chunk transforms in place:
//   out[2f]   = (in[f] + in[f+256]) * INV_SQRT2
//   out[2f+1] = (in[f] - in[f+256]) * INV_SQRT2
//
// FINAL (R8 = R4 config, best measured): one-shot launch, 512-thread blocks,
// per thread: 2x dense LDG.E.256 + 2x dense STG.E.256, .cs single-touch
// policy throughout. Each warp instruction covers a contiguous 1KB span;
// the cA/cD interleave is resolved entirely in registers.
//
// Measured: 73.8us kernel, DRAM 82.8%, useful traffic 7.27 TB/s (~91% of
// 8TB/s spec) — HBM read/write-turnaround limited. Rejected by measurement:
// 4-load ILP (occupancy loss, R5), .lu policy (neutral, R6), persistent
// grid-stride (serialized loop, lost cross-wave MLP, R7).

__global__ void __launch_bounds__(512) haar_kernel(
    const float* __restrict__ in,
    float* __restrict__ out,
    int nt)                           // total threads = out floats / 16
{
    int t = blockIdx.x * blockDim.x + threadIdx.x;
    if (t >= nt) return;

    const float c = 0.70710678118654752440f;

    int chunk = t >> 5;               // 32 lanes cover one 512-float chunk
    int j     = t & 31;

    const float* p0 = in + ((long)chunk << 9) + (j << 3);   // x0: 8 floats
    const float* p1 = p0 + 256;                             // x1: 8 floats

    float a0,a1,a2,a3,a4,a5,a6,a7;
    float b0,b1,b2,b3,b4,b5,b6,b7;

    asm volatile("ld.global.cs.v8.f32 {%0,%1,%2,%3,%4,%5,%6,%7}, [%8];"
        : "=f"(a0),"=f"(a1),"=f"(a2),"=f"(a3),
          "=f"(a4),"=f"(a5),"=f"(a6),"=f"(a7)
        : "l"(p0));
    asm volatile("ld.global.cs.v8.f32 {%0,%1,%2,%3,%4,%5,%6,%7}, [%8];"
        : "=f"(b0),"=f"(b1),"=f"(b2),"=f"(b3),
          "=f"(b4),"=f"(b5),"=f"(b6),"=f"(b7)
        : "l"(p1));

    float* q = out + ((long)chunk << 9) + (j << 4);         // 16 contiguous outputs

    float o0 = (a0 + b0) * c, o1 = (a0 - b0) * c;
    float o2 = (a1 + b1) * c, o3 = (a1 - b1) * c;
    float o4 = (a2 + b2) * c, o5 = (a2 - b2) * c;
    float o6 = (a3 + b3) * c, o7 = (a3 - b3) * c;

    asm volatile("st.global.cs.v8.f32 [%0], {%1,%2,%3,%4,%5,%6,%7,%8};"
        :: "l"(q),
           "f"(o0),"f"(o1),"f"(o2),"f"(o3),
           "f"(o4),"f"(o5),"f"(o6),"f"(o7)
        : "memory");

    float s0 = (a4 + b4) * c, s1 = (a4 - b4) * c;
    float s2 = (a5 + b5) * c, s3 = (a5 - b5) * c;
    float s4 = (a6 + b6) * c, s5 = (a6 - b6) * c;
    float s6 = (a7 + b7) * c, s7 = (a7 - b7) * c;

    asm volatile("st.global.cs.v8.f32 [%0], {%1,%2,%3,%4,%5,%6,%7,%8};"
        :: "l"(q + 8),
           "f"(s0),"f"(s1),"f"(s2),"f"(s3),
           "f"(s4),"f"(s5),"f"(s6),"f"(s7)
        : "memory");
}

extern "C" void kernel_launch(void* const* d_in, const int* in_sizes, int n_in,
                              void* d_out, int out_size)
{
    const float* x = (const float*)d_in[0];
    float* out = (float*)d_out;

    int nt = out_size / 16;                      // 4,194,304 threads (16 floats out each)
    int threads = 512;
    int blocks = (nt + threads - 1) / threads;   // 8,192 blocks

    haar_kernel<<<blocks, threads>>>(x, out, nt);
}

// round 9
// speedup vs baseline: 1.1191x; 1.0055x over previous
#include <cuda_runtime.h>

// Haar pair transform: x (64, 4096, 256) f32 -> out (64, 2048, 512) f32
// Chunk-local identity mapping: each contiguous 512-float chunk transforms in place:
//   out[2f]   = (in[f] + in[f+256]) * INV_SQRT2
//   out[2f+1] = (in[f] - in[f+256]) * INV_SQRT2
//
// FINAL: one-shot launch, 512-thread blocks; per thread 2x dense LDG.E.256
// (.lu last-use — single-touch read stream) + 2x dense STG.E.256 (.cs
// evict-first). Every warp-level memory instruction covers a contiguous 1KB
// span; the cA/cD interleave is resolved entirely in registers, so the
// stride-2 output pattern never reaches the memory system.
//
// Measured across 5 runs of this family: kernel 73.8-74.7us, DRAM active
// 82+-1%, useful traffic ~7.25 TB/s (~91% of 8 TB/s spec) — HBM read/write
// turnaround limited. Rejected by measurement: 4-load ILP (occupancy loss),
// persistent grid-stride (serialized loop, lost cross-wave MLP), wider/
// narrower blocks, cache-policy variants (all within noise).

__global__ void __launch_bounds__(512) haar_kernel(
    const float* __restrict__ in,
    float* __restrict__ out,
    int nt)                           // total threads = out floats / 16
{
    int t = blockIdx.x * blockDim.x + threadIdx.x;
    if (t >= nt) return;

    const float c = 0.70710678118654752440f;

    int chunk = t >> 5;               // 32 lanes cover one 512-float chunk
    int j     = t & 31;

    const float* p0 = in + ((long)chunk << 9) + (j << 3);   // x0: 8 floats
    const float* p1 = p0 + 256;                             // x1: 8 floats

    float a0,a1,a2,a3,a4,a5,a6,a7;
    float b0,b1,b2,b3,b4,b5,b6,b7;

    asm volatile("ld.global.lu.v8.f32 {%0,%1,%2,%3,%4,%5,%6,%7}, [%8];"
        : "=f"(a0),"=f"(a1),"=f"(a2),"=f"(a3),
          "=f"(a4),"=f"(a5),"=f"(a6),"=f"(a7)
        : "l"(p0));
    asm volatile("ld.global.lu.v8.f32 {%0,%1,%2,%3,%4,%5,%6,%7}, [%8];"
        : "=f"(b0),"=f"(b1),"=f"(b2),"=f"(b3),
          "=f"(b4),"=f"(b5),"=f"(b6),"=f"(b7)
        : "l"(p1));

    float* q = out + ((long)chunk << 9) + (j << 4);         // 16 contiguous outputs

    float o0 = (a0 + b0) * c, o1 = (a0 - b0) * c;
    float o2 = (a1 + b1) * c, o3 = (a1 - b1) * c;
    float o4 = (a2 + b2) * c, o5 = (a2 - b2) * c;
    float o6 = (a3 + b3) * c, o7 = (a3 - b3) * c;

    asm volatile("st.global.cs.v8.f32 [%0], {%1,%2,%3,%4,%5,%6,%7,%8};"
        :: "l"(q),
           "f"(o0),"f"(o1),"f"(o2),"f"(o3),
           "f"(o4),"f"(o5),"f"(o6),"f"(o7)
        : "memory");

    float s0 = (a4 + b4) * c, s1 = (a4 - b4) * c;
    float s2 = (a5 + b5) * c, s3 = (a5 - b5) * c;
    float s4 = (a6 + b6) * c, s5 = (a6 - b6) * c;
    float s6 = (a7 + b7) * c, s7 = (a7 - b7) * c;

    asm volatile("st.global.cs.v8.f32 [%0], {%1,%2,%3,%4,%5,%6,%7,%8};"
        :: "l"(q + 8),
           "f"(s0),"f"(s1),"f"(s2),"f"(s3),
           "f"(s4),"f"(s5),"f"(s6),"f"(s7)
        : "memory");
}

extern "C" void kernel_launch(void* const* d_in, const int* in_sizes, int n_in,
                              void* d_out, int out_size)
{
    const float* x = (const float*)d_in[0];
    float* out = (float*)d_out;

    int nt = out_size / 16;                      // 4,194,304 threads (16 floats out each)
    int threads = 512;
    int blocks = (nt + threads - 1) / threads;   // 8,192 blocks

    haar_kernel<<<blocks, threads>>>(x, out, nt);
}